// round 7
// baseline (speedup 1.0000x reference)
#include <cuda_runtime.h>
#include <cstdint>

#define NB    24
#define NP1   25
#define NCOST (NB * NP1)      // 600 floats per batch
#define ND    256
#define INFX  1e9f
#define FULL  0xffffffffu
#define MAXB  2048
#define NCHUNK 2

// cost scratch: [B][24][25] fp32 (~4.9 MB), static device array (no allocs)
__device__ float g_cost[(size_t)MAXB * NCOST];

// ---- stream/event infrastructure, created BEFORE harness checkpoints ----
namespace {
struct PipeInit {
    cudaStream_t s2 = nullptr;
    cudaEvent_t  ev_fork = nullptr;
    cudaEvent_t  ev_cost[NCHUNK] = {};
    cudaEvent_t  ev_join = nullptr;
    PipeInit() {
        cudaStreamCreateWithFlags(&s2, cudaStreamNonBlocking);
        cudaEventCreateWithFlags(&ev_fork, cudaEventDisableTiming);
        for (int i = 0; i < NCHUNK; i++)
            cudaEventCreateWithFlags(&ev_cost[i], cudaEventDisableTiming);
        cudaEventCreateWithFlags(&ev_join, cudaEventDisableTiming);
    }
};
PipeInit g_pipe;
}

// packed fp32x2 FMA (sm_100+); doubles are 64-bit carriers for f32 pairs
__device__ __forceinline__ double ffma2(double a, double b, double c) {
    double r;
    asm("fma.rn.f32x2 %0, %1, %2, %3;" : "=d"(r) : "d"(a), "d"(b), "d"(c));
    return r;
}
__device__ __forceinline__ float pairsum(double a) {
    return __int_as_float(__double2loint(a)) + __int_as_float(__double2hiint(a));
}
// order-preserving float<->uint for unsigned min-reduction
__device__ __forceinline__ unsigned fenc(float x) {
    unsigned b = __float_as_uint(x);
    return b ^ (((unsigned)((int)b >> 31)) | 0x80000000u);
}
__device__ __forceinline__ float fdec(unsigned k) {
    unsigned m = ((unsigned)((int)(~k) >> 31)) | 0x80000000u;
    return __uint_as_float(k ^ m);
}

// 8-stream folded warp reduction: lane L ends holding the full sum of stream
// m(L) = bit4(L) | bit3(L)<<1 | bit2(L)<<2. 15 shfls, 8-wide ILP at the top.
__device__ __forceinline__ float fold8(
    float q0, float q1, float q2, float q3,
    float q4, float q5, float q6, float q7, int lane)
{
    q0 += __shfl_xor_sync(FULL, q0, 16);
    q1 += __shfl_xor_sync(FULL, q1, 16);
    q2 += __shfl_xor_sync(FULL, q2, 16);
    q3 += __shfl_xor_sync(FULL, q3, 16);
    q4 += __shfl_xor_sync(FULL, q4, 16);
    q5 += __shfl_xor_sync(FULL, q5, 16);
    q6 += __shfl_xor_sync(FULL, q6, 16);
    q7 += __shfl_xor_sync(FULL, q7, 16);
    float t0 = (lane & 16) ? q1 : q0;
    float t1 = (lane & 16) ? q3 : q2;
    float t2 = (lane & 16) ? q5 : q4;
    float t3 = (lane & 16) ? q7 : q6;
    t0 += __shfl_xor_sync(FULL, t0, 8);
    t1 += __shfl_xor_sync(FULL, t1, 8);
    t2 += __shfl_xor_sync(FULL, t2, 8);
    t3 += __shfl_xor_sync(FULL, t3, 8);
    float u0 = (lane & 8) ? t1 : t0;
    float u1 = (lane & 8) ? t3 : t2;
    u0 += __shfl_xor_sync(FULL, u0, 4);
    u1 += __shfl_xor_sync(FULL, u1, 4);
    float v = (lane & 4) ? u1 : u0;
    v += __shfl_xor_sync(FULL, v, 2);
    v += __shfl_xor_sync(FULL, v, 1);
    return v;
}

// ============================================================================
// Kernel 1 (cost): CTA = one batch, 192 threads (6 warps). Unchanged from the
// validated R6 version except it takes a batch offset for chunking.
// ============================================================================
__global__ __launch_bounds__(192) void costk(
    const float* __restrict__ slots,
    const float* __restrict__ prev,
    int b0)
{
    __shared__ float ipn_s[NB];
    __shared__ float icn_s[NB];

    const int tid  = threadIdx.x;
    const int lane = tid & 31;
    const int w    = tid >> 5;           // 0..5
    const int b    = b0 + blockIdx.x;

    const float* sb = slots + (size_t)b * NB * ND;
    const float* pb = prev  + (size_t)b * NB * ND;

    // ---- prev i-block into registers + all inverse norms (one fold8) ----
    const int i0 = w * 4;
    double2 P[4][2];
    {
        float np[4], nc[4];
        #pragma unroll
        for (int r = 0; r < 4; r++) {
            const double2* pr = (const double2*)(pb + (i0 + r) * ND);
            P[r][0] = pr[lane];
            P[r][1] = pr[lane + 32];
            double an = 0.0;
            an = ffma2(P[r][0].x, P[r][0].x, an);
            an = ffma2(P[r][0].y, P[r][0].y, an);
            an = ffma2(P[r][1].x, P[r][1].x, an);
            an = ffma2(P[r][1].y, P[r][1].y, an);
            np[r] = pairsum(an);
            const double2* cr = (const double2*)(sb + (i0 + r) * ND);
            double2 c0 = cr[lane], c1 = cr[lane + 32];
            double cn = 0.0;
            cn = ffma2(c0.x, c0.x, cn);
            cn = ffma2(c0.y, c0.y, cn);
            cn = ffma2(c1.x, c1.x, cn);
            cn = ffma2(c1.y, c1.y, cn);
            nc[r] = pairsum(cn);
        }
        float v3 = fold8(np[0], np[1], np[2], np[3],
                         nc[0], nc[1], nc[2], nc[3], lane);
        float inv = 1.0f / fmaxf(sqrtf(v3), 1e-12f);
        if ((lane & 3) == 0) {
            int m = ((lane >> 4) & 1) | (((lane >> 3) & 1) << 1) | (((lane >> 2) & 1) << 2);
            if (m < 4) ipn_s[i0 + m]       = inv;
            else       icn_s[i0 + (m - 4)] = inv;
        }
    }
    __syncthreads();

    // ---- 6 j-blocks of 4 cur rows (global/L1), two 8-dot halves each ----
    {
        const int m = ((lane >> 4) & 1) | (((lane >> 3) & 1) << 1) | (((lane >> 2) & 1) << 2);
        const int a = m >> 2;       // 0..1
        const int c = m & 3;        // 0..3
        const bool writer = ((lane & 3) == 0);
        float ipn1 = 0.f, ipn2 = 0.f;
        if (writer) {
            ipn1 = ipn_s[i0 + a];
            ipn2 = ipn_s[i0 + 2 + a];
        }
        float* gc = g_cost + (size_t)b * NCOST;

        #pragma unroll
        for (int t = 0; t < 6; t++) {
            const int j0 = t * 4;
            double2 C0[4], C1[4];
            #pragma unroll
            for (int r = 0; r < 4; r++) {
                const double2* cr = (const double2*)(sb + (j0 + r) * ND);
                C0[r] = cr[lane];
                C1[r] = cr[lane + 32];
            }
            {
                float s[8];
                #pragma unroll
                for (int aa = 0; aa < 2; aa++) {
                    #pragma unroll
                    for (int cc = 0; cc < 4; cc++) {
                        double acc = 0.0;
                        acc = ffma2(P[aa][0].x, C0[cc].x, acc);
                        acc = ffma2(P[aa][0].y, C0[cc].y, acc);
                        acc = ffma2(P[aa][1].x, C1[cc].x, acc);
                        acc = ffma2(P[aa][1].y, C1[cc].y, acc);
                        s[aa * 4 + cc] = pairsum(acc);
                    }
                }
                float v1 = fold8(s[0], s[1], s[2], s[3], s[4], s[5], s[6], s[7], lane);
                if (writer)
                    gc[(i0 + a) * NP1 + (j0 + c)] = 1.0f - v1 * ipn1 * icn_s[j0 + c];
            }
            {
                float s[8];
                #pragma unroll
                for (int aa = 0; aa < 2; aa++) {
                    #pragma unroll
                    for (int cc = 0; cc < 4; cc++) {
                        double acc = 0.0;
                        acc = ffma2(P[2 + aa][0].x, C0[cc].x, acc);
                        acc = ffma2(P[2 + aa][0].y, C0[cc].y, acc);
                        acc = ffma2(P[2 + aa][1].x, C1[cc].x, acc);
                        acc = ffma2(P[2 + aa][1].y, C1[cc].y, acc);
                        s[aa * 4 + cc] = pairsum(acc);
                    }
                }
                float v2 = fold8(s[0], s[1], s[2], s[3], s[4], s[5], s[6], s[7], lane);
                if (writer)
                    gc[(i0 + 2 + a) * NP1 + (j0 + c)] = 1.0f - v2 * ipn2 * icn_s[j0 + c];
            }
        }
    }
}

// ---- validated JV row step: search one augmenting path for row i and augment.
// State lives in lane registers (u, v, p) + smem cost. Byte-identical
// arithmetic to the R2..R6 formulation.
struct JVState {
    float u, v;
    int   p;
};
__device__ __forceinline__ void jv_row(
    JVState& st, const float* __restrict__ cw, int i, int lane, unsigned ENC_INF)
{
    if (lane == NB) st.p = i;        // virtual start column holds new row
    float minv = INFX;
    int   way  = 0;
    bool  used = false;
    bool  row_used = false;
    int   j0  = NB;
    int   pj0 = i;

    while (true) {
        used     = used     || (lane == j0);
        row_used = row_used || (lane == pj0);
        float u_i0 = __shfl_sync(FULL, st.u, pj0);
        float crow = (lane < NB) ? cw[pj0 * NP1 + lane] : 0.0f;
        bool  act  = (lane < NB) && !used;
        float cv   = crow - u_i0 - st.v;     // reduced cost
        if (act && cv < minv) { minv = cv; way = j0; }
        unsigned key  = act ? fenc(minv) : ENC_INF;
        unsigned kmin = __reduce_min_sync(FULL, key);
        int j1 = __ffs(__ballot_sync(FULL, key == kmin)) - 1;
        float delta = fdec(kmin);
        if (used)     st.v -= delta;
        if (row_used) st.u += delta;
        if (act)      minv -= delta;
        j0  = j1;
        pj0 = __shfl_sync(FULL, st.p, j0);
        if (pj0 < 0) break;          // reached a free column
    }
    while (j0 != NB) {               // augment back to virtual column
        int jp = __shfl_sync(FULL, way, j0);
        int pv = __shfl_sync(FULL, st.p, jp);
        if (lane == j0) st.p = pv;
        j0 = jp;
    }
}

// ============================================================================
// Kernel 2: JV + gather, TWO batches per warp (row-level interleave for
// latency overlap). 4 warps/CTA -> 8 batches/CTA. No __syncthreads.
// ============================================================================
__global__ __launch_bounds__(128) void jvk(
    const float* __restrict__ slots,
    float* __restrict__ out,
    int b0, int nb)
{
    __shared__ float cost_s[8][NCOST];
    __shared__ int   col_s[8][NB];

    const int lane = threadIdx.x & 31;
    const int w    = threadIdx.x >> 5;
    const int bA   = b0 + blockIdx.x * 8 + w * 2;       // first batch of pair
    const int bB   = bA + 1;
    const bool hasA = (bA - b0) < nb;
    const bool hasB = (bB - b0) < nb;
    if (!hasA) return;

    // ---- stage cost matrices for both batches ----
    {
        const float4* gA = (const float4*)(g_cost + (size_t)bA * NCOST);
        float4* cA = (float4*)cost_s[w * 2];
        #pragma unroll
        for (int t = lane; t < NCOST / 4; t += 32) cA[t] = gA[t];
        if (hasB) {
            const float4* gB = (const float4*)(g_cost + (size_t)bB * NCOST);
            float4* cB = (float4*)cost_s[w * 2 + 1];
            #pragma unroll
            for (int t = lane; t < NCOST / 4; t += 32) cB[t] = gB[t];
        }
    }
    __syncwarp();

    // ---- interleaved JV: row i of A, then row i of B ----
    {
        const unsigned ENC_INF = fenc(INFX);
        JVState sA = {0.0f, 0.0f, -1};
        JVState sB = {0.0f, 0.0f, -1};
        const float* cwA = cost_s[w * 2];
        const float* cwB = cost_s[w * 2 + 1];
        for (int i = 0; i < NB; i++) {
            jv_row(sA, cwA, i, lane, ENC_INF);
            if (hasB) jv_row(sB, cwB, i, lane, ENC_INF);
        }
        if (lane < NB) {
            col_s[w * 2][sA.p] = lane;
            if (hasB) col_s[w * 2 + 1][sB.p] = lane;
        }
    }
    __syncwarp();

    // ---- gather both batches ----
    #pragma unroll
    for (int pairi = 0; pairi < 2; pairi++) {
        if (pairi == 1 && !hasB) break;
        const int b = bA + pairi;
        const float* sb = slots + (size_t)b * NB * ND;
        float*       ob = out   + (size_t)b * NB * ND;
        const int*   cs = col_s[w * 2 + pairi];
        for (int rr = 0; rr < NB; rr++) {
            int src = cs[rr];
            const float4* s4 = (const float4*)(sb + src * ND);
            float4*       o4 = (float4*)(ob + rr * ND);
            o4[lane]      = s4[lane];
            o4[lane + 32] = s4[lane + 32];
        }
    }
}

extern "C" void kernel_launch(void* const* d_in, const int* in_sizes, int n_in,
                              void* d_out, int out_size) {
    const float* slots = (const float*)d_in[0];
    const float* prev  = (const float*)d_in[1];
    float* out = (float*)d_out;
    int B = in_sizes[0] / (NB * ND);
    if (B > MAXB) B = MAXB;

    // fork second stream off the (capturing) default stream
    cudaEventRecord(g_pipe.ev_fork, 0);
    cudaStreamWaitEvent(g_pipe.s2, g_pipe.ev_fork, 0);

    int chunk = (B + NCHUNK - 1) / NCHUNK;
    for (int c = 0; c < NCHUNK; c++) {
        int b0 = c * chunk;
        int nb = (b0 + chunk <= B) ? chunk : (B - b0);
        if (nb <= 0) break;
        costk<<<nb, 192>>>(slots, prev, b0);
        cudaEventRecord(g_pipe.ev_cost[c], 0);
        cudaStreamWaitEvent(g_pipe.s2, g_pipe.ev_cost[c], 0);
        int grid2 = (nb + 7) / 8;   // 8 batches per CTA (2 per warp)
        jvk<<<grid2, 128, 0, g_pipe.s2>>>(slots, out, b0, nb);
    }

    // join back to the default (capturing) stream
    cudaEventRecord(g_pipe.ev_join, g_pipe.s2);
    cudaStreamWaitEvent(0, g_pipe.ev_join, 0);
}

// round 8
// speedup vs baseline: 2.1311x; 2.1311x over previous
#include <cuda_runtime.h>
#include <cstdint>

#define NB    24
#define NP1   25
#define NCOST (NB * NP1)      // 600 floats per batch
#define ND    256
#define INFX  1e9f
#define FULL  0xffffffffu
#define MAXB  2048

// cost scratch: [B][24][25] fp32 (~4.9 MB), static device array (no allocs)
__device__ float g_cost[(size_t)MAXB * NCOST];

// packed fp32x2 FMA (sm_100+); doubles are 64-bit carriers for f32 pairs
__device__ __forceinline__ double ffma2(double a, double b, double c) {
    double r;
    asm("fma.rn.f32x2 %0, %1, %2, %3;" : "=d"(r) : "d"(a), "d"(b), "d"(c));
    return r;
}
__device__ __forceinline__ float pairsum(double a) {
    return __int_as_float(__double2loint(a)) + __int_as_float(__double2hiint(a));
}
// order-preserving float<->uint for unsigned min-reduction
__device__ __forceinline__ unsigned fenc(float x) {
    unsigned b = __float_as_uint(x);
    return b ^ (((unsigned)((int)b >> 31)) | 0x80000000u);
}
__device__ __forceinline__ float fdec(unsigned k) {
    unsigned m = ((unsigned)((int)(~k) >> 31)) | 0x80000000u;
    return __uint_as_float(k ^ m);
}

// 8-stream folded warp reduction: lane L ends holding the full sum of stream
// m(L) = bit4(L) | bit3(L)<<1 | bit2(L)<<2. 15 shfls, 8-wide ILP at the top.
__device__ __forceinline__ float fold8(
    float q0, float q1, float q2, float q3,
    float q4, float q5, float q6, float q7, int lane)
{
    q0 += __shfl_xor_sync(FULL, q0, 16);
    q1 += __shfl_xor_sync(FULL, q1, 16);
    q2 += __shfl_xor_sync(FULL, q2, 16);
    q3 += __shfl_xor_sync(FULL, q3, 16);
    q4 += __shfl_xor_sync(FULL, q4, 16);
    q5 += __shfl_xor_sync(FULL, q5, 16);
    q6 += __shfl_xor_sync(FULL, q6, 16);
    q7 += __shfl_xor_sync(FULL, q7, 16);
    float t0 = (lane & 16) ? q1 : q0;
    float t1 = (lane & 16) ? q3 : q2;
    float t2 = (lane & 16) ? q5 : q4;
    float t3 = (lane & 16) ? q7 : q6;
    t0 += __shfl_xor_sync(FULL, t0, 8);
    t1 += __shfl_xor_sync(FULL, t1, 8);
    t2 += __shfl_xor_sync(FULL, t2, 8);
    t3 += __shfl_xor_sync(FULL, t3, 8);
    float u0 = (lane & 8) ? t1 : t0;
    float u1 = (lane & 8) ? t3 : t2;
    u0 += __shfl_xor_sync(FULL, u0, 4);
    u1 += __shfl_xor_sync(FULL, u1, 4);
    float v = (lane & 4) ? u1 : u0;
    v += __shfl_xor_sync(FULL, v, 2);
    v += __shfl_xor_sync(FULL, v, 1);
    return v;
}

// ============================================================================
// Kernel 1 (cost): CTA = one batch, 192 threads (6 warps). Validated R6.
// ============================================================================
__global__ __launch_bounds__(192) void costk(
    const float* __restrict__ slots,
    const float* __restrict__ prev,
    int B)
{
    __shared__ float ipn_s[NB];
    __shared__ float icn_s[NB];

    const int tid  = threadIdx.x;
    const int lane = tid & 31;
    const int w    = tid >> 5;           // 0..5
    const int b    = blockIdx.x;

    const float* sb = slots + (size_t)b * NB * ND;
    const float* pb = prev  + (size_t)b * NB * ND;

    // ---- prev i-block into registers + all inverse norms (one fold8) ----
    const int i0 = w * 4;
    double2 P[4][2];
    {
        float np[4], nc[4];
        #pragma unroll
        for (int r = 0; r < 4; r++) {
            const double2* pr = (const double2*)(pb + (i0 + r) * ND);
            P[r][0] = pr[lane];
            P[r][1] = pr[lane + 32];
            double an = 0.0;
            an = ffma2(P[r][0].x, P[r][0].x, an);
            an = ffma2(P[r][0].y, P[r][0].y, an);
            an = ffma2(P[r][1].x, P[r][1].x, an);
            an = ffma2(P[r][1].y, P[r][1].y, an);
            np[r] = pairsum(an);
            const double2* cr = (const double2*)(sb + (i0 + r) * ND);
            double2 c0 = cr[lane], c1 = cr[lane + 32];
            double cn = 0.0;
            cn = ffma2(c0.x, c0.x, cn);
            cn = ffma2(c0.y, c0.y, cn);
            cn = ffma2(c1.x, c1.x, cn);
            cn = ffma2(c1.y, c1.y, cn);
            nc[r] = pairsum(cn);
        }
        float v3 = fold8(np[0], np[1], np[2], np[3],
                         nc[0], nc[1], nc[2], nc[3], lane);
        float inv = 1.0f / fmaxf(sqrtf(v3), 1e-12f);
        if ((lane & 3) == 0) {
            int m = ((lane >> 4) & 1) | (((lane >> 3) & 1) << 1) | (((lane >> 2) & 1) << 2);
            if (m < 4) ipn_s[i0 + m]       = inv;
            else       icn_s[i0 + (m - 4)] = inv;
        }
    }
    __syncthreads();

    // ---- 6 j-blocks of 4 cur rows (global/L1), two 8-dot halves each ----
    {
        const int m = ((lane >> 4) & 1) | (((lane >> 3) & 1) << 1) | (((lane >> 2) & 1) << 2);
        const int a = m >> 2;       // 0..1
        const int c = m & 3;        // 0..3
        const bool writer = ((lane & 3) == 0);
        float ipn1 = 0.f, ipn2 = 0.f;
        if (writer) {
            ipn1 = ipn_s[i0 + a];
            ipn2 = ipn_s[i0 + 2 + a];
        }
        float* gc = g_cost + (size_t)b * NCOST;

        #pragma unroll
        for (int t = 0; t < 6; t++) {
            const int j0 = t * 4;
            double2 C0[4], C1[4];
            #pragma unroll
            for (int r = 0; r < 4; r++) {
                const double2* cr = (const double2*)(sb + (j0 + r) * ND);
                C0[r] = cr[lane];
                C1[r] = cr[lane + 32];
            }
            {
                float s[8];
                #pragma unroll
                for (int aa = 0; aa < 2; aa++) {
                    #pragma unroll
                    for (int cc = 0; cc < 4; cc++) {
                        double acc = 0.0;
                        acc = ffma2(P[aa][0].x, C0[cc].x, acc);
                        acc = ffma2(P[aa][0].y, C0[cc].y, acc);
                        acc = ffma2(P[aa][1].x, C1[cc].x, acc);
                        acc = ffma2(P[aa][1].y, C1[cc].y, acc);
                        s[aa * 4 + cc] = pairsum(acc);
                    }
                }
                float v1 = fold8(s[0], s[1], s[2], s[3], s[4], s[5], s[6], s[7], lane);
                if (writer)
                    gc[(i0 + a) * NP1 + (j0 + c)] = 1.0f - v1 * ipn1 * icn_s[j0 + c];
            }
            {
                float s[8];
                #pragma unroll
                for (int aa = 0; aa < 2; aa++) {
                    #pragma unroll
                    for (int cc = 0; cc < 4; cc++) {
                        double acc = 0.0;
                        acc = ffma2(P[2 + aa][0].x, C0[cc].x, acc);
                        acc = ffma2(P[2 + aa][0].y, C0[cc].y, acc);
                        acc = ffma2(P[2 + aa][1].x, C1[cc].x, acc);
                        acc = ffma2(P[2 + aa][1].y, C1[cc].y, acc);
                        s[aa * 4 + cc] = pairsum(acc);
                    }
                }
                float v2 = fold8(s[0], s[1], s[2], s[3], s[4], s[5], s[6], s[7], lane);
                if (writer)
                    gc[(i0 + 2 + a) * NP1 + (j0 + c)] = 1.0f - v2 * ipn2 * icn_s[j0 + c];
            }
        }
    }
}

// ============================================================================
// Kernel 2: JV Hungarian + gather. One warp per batch, 4 warps/CTA.
// NEW: classic JV column-reduction initialization (v[j] = col min, greedy
// unique-argmin matching), then the VALIDATED shortest-augmenting-path search
// runs only for the remaining free rows (~9 of 24). Duals stay dual-feasible
// with zero reduced cost on matched pairs, so the search is exact; the unique
// optimal assignment is unchanged.
// ============================================================================
__global__ __launch_bounds__(128) void jvk(
    const float* __restrict__ slots,
    float* __restrict__ out,
    int B)
{
    __shared__ float cost_s[4][NCOST];
    __shared__ int   col_s[4][NB];

    const int lane = threadIdx.x & 31;
    const int w    = threadIdx.x >> 5;
    const int b    = blockIdx.x * 4 + w;
    if (b >= B) return;

    // ---- stage this batch's cost matrix into smem (600 floats) ----
    {
        const float4* gc4 = (const float4*)(g_cost + (size_t)b * NCOST);
        float4* cs4 = (float4*)cost_s[w];
        #pragma unroll
        for (int t = lane; t < NCOST / 4; t += 32)
            cs4[t] = gc4[t];
    }
    __syncwarp();

    const float* cw = cost_s[w];
    const unsigned ENC_INF = fenc(INFX);

    float u = 0.0f, v = 0.0f;
    int   p = -1;
    unsigned rowmask = 0;       // bit r set => row r matched

    // ---- column reduction: v[j] = min_i c[i][j]; greedy argmin matching ----
    {
        int rmin = 32 + lane;   // unique sentinel for lanes >= NB
        if (lane < NB) {
            float m = INFX;
            rmin = 0;
            #pragma unroll
            for (int i = 0; i < NB; i++) {
                float c = cw[i * NP1 + lane];
                if (c < m) { m = c; rmin = i; }   // first-index on ties
            }
            v = m;
        }
        unsigned grp = __match_any_sync(FULL, rmin);
        bool claim = (lane < NB) && (lane == __ffs(grp) - 1);  // lowest col wins row
        if (claim) p = rmin;
        rowmask = __reduce_or_sync(FULL, claim ? (1u << rmin) : 0u);
    }

    // ---- augmenting-path searches for free rows (validated formulation) ----
    for (int i = 0; i < NB; i++) {
        if ((rowmask >> i) & 1u) continue;     // row already matched

        if (lane == NB) p = i;        // virtual start column holds new row
        float minv = INFX;
        int   way  = 0;
        bool  used = false;
        bool  row_used = false;
        int   j0  = NB;
        int   pj0 = i;

        while (true) {
            used     = used     || (lane == j0);
            row_used = row_used || (lane == pj0);
            float u_i0 = __shfl_sync(FULL, u, pj0);
            float crow = (lane < NB) ? cw[pj0 * NP1 + lane] : 0.0f;
            bool  act  = (lane < NB) && !used;
            if (act) {
                float cv = crow - u_i0 - v;       // reduced cost
                if (cv < minv) { minv = cv; way = j0; }
            }
            unsigned key  = act ? fenc(minv) : ENC_INF;
            unsigned kmin = __reduce_min_sync(FULL, key);
            int j1 = __ffs(__ballot_sync(FULL, key == kmin)) - 1;
            float delta = fdec(kmin);
            if (used)     v    -= delta;
            if (row_used) u    += delta;
            if (act)      minv -= delta;
            j0  = j1;
            pj0 = __shfl_sync(FULL, p, j0);
            if (pj0 < 0) break;      // reached a free column
        }
        // augment along parent pointers back to virtual column
        while (j0 != NB) {
            int jp = __shfl_sync(FULL, way, j0);
            int pv = __shfl_sync(FULL, p, jp);
            if (lane == j0) p = pv;
            j0 = jp;
        }
    }
    if (lane < NB) col_s[w][p] = lane;   // col index of row p[j] is j
    __syncwarp();

    // ---- gather: out[row][:] = slots[col[row]][:] ----
    const float* sb = slots + (size_t)b * NB * ND;
    float*       ob = out   + (size_t)b * NB * ND;
    for (int rr = 0; rr < NB; rr++) {
        int src = col_s[w][rr];
        const float4* s4 = (const float4*)(sb + src * ND);
        float4*       o4 = (float4*)(ob + rr * ND);
        o4[lane]      = s4[lane];
        o4[lane + 32] = s4[lane + 32];
    }
}

extern "C" void kernel_launch(void* const* d_in, const int* in_sizes, int n_in,
                              void* d_out, int out_size) {
    const float* slots = (const float*)d_in[0];
    const float* prev  = (const float*)d_in[1];
    float* out = (float*)d_out;
    int B = in_sizes[0] / (NB * ND);
    if (B > MAXB) B = MAXB;

    costk<<<B, 192>>>(slots, prev, B);

    int grid2 = (B + 3) / 4;
    jvk<<<grid2, 128>>>(slots, out, B);
}